// round 13
// baseline (speedup 1.0000x reference)
#include <cuda_runtime.h>
#include <cuda_fp16.h>

#define C_IN   10
#define C_OUT  64
#define MAXM   200000
#define MAXN   2000000
#define MAXPTS 64
#define W_BEV  512
#define H_BEV  512
#define NSLOT  (4 * W_BEV * H_BEV)
#define FULLMASK 0xffffffffu

// ---- device scratch (statics; zero at load; every replay self-resets) ----
__device__ __align__(16) int   g_cnt[MAXM];                   // zeroed by k_pillar after use
__device__ __align__(16) int   g_order[MAXM * MAXPTS];        // 51.2 MB
__device__ __align__(16) float g_s[(long long)MAXN * C_OUT];  // 512 MB
__device__ __align__(16) float g_pf[(long long)MAXM * C_OUT]; // 51.2 MB
__device__ __align__(16) int   g_slot[NSLOT];                 // pillar+1; reset by k_scatter
__device__ __align__(16) float g_xsum[C_IN];                  // zeroed by k_bn after use
__device__ __align__(16) float g_xcov[55];                    // zeroed by k_bn after use
__device__ __align__(16) float g_a[C_OUT];
__device__ __align__(16) float g_b[C_OUT];

// ---- packed f32x2 helpers ----
typedef unsigned long long u64;
typedef unsigned int u32;
__device__ __forceinline__ u64 pk2(float lo, float hi) {
    u64 r; asm("mov.b64 %0, {%1,%2};" : "=l"(r) : "f"(lo), "f"(hi)); return r;
}
__device__ __forceinline__ void upk2(u64 v, float& lo, float& hi) {
    asm("mov.b64 {%0,%1}, %2;" : "=f"(lo), "=f"(hi) : "l"(v));
}
__device__ __forceinline__ u64 fma2(u64 a, u64 b, u64 c) {
    u64 d; asm("fma.rn.f32x2 %0, %1, %2, %3;" : "=l"(d) : "l"(a), "l"(b), "l"(c)); return d;
}

// ---- fp16 m16n8k16 mma, f32 accumulate ----
__device__ __forceinline__ void mma16(float d[4], const u32 a[4], const u32 b[2]) {
    asm volatile("mma.sync.aligned.m16n8k16.row.col.f32.f16.f16.f32 "
        "{%0,%1,%2,%3},{%4,%5,%6,%7},{%8,%9},{%0,%1,%2,%3};"
        : "+f"(d[0]), "+f"(d[1]), "+f"(d[2]), "+f"(d[3])
        : "r"(a[0]), "r"(a[1]), "r"(a[2]), "r"(a[3]), "r"(b[0]), "r"(b[1]));
}

// ---------------------------------------------------------------------------
// K1: x first/second moments ONLY (block-level reduction, 65 atomics/block)
// ---------------------------------------------------------------------------
__global__ void __launch_bounds__(256) k_mom(const float* __restrict__ gf, int N)
{
    __shared__ float red[8][65];
    float sx[C_IN];
    float sxx[55];
#pragma unroll
    for (int i = 0; i < C_IN; i++) sx[i] = 0.f;
#pragma unroll
    for (int i = 0; i < 55; i++) sxx[i] = 0.f;

    const int stride = gridDim.x * blockDim.x;
    for (int p = blockIdx.x * blockDim.x + threadIdx.x; p < N; p += stride) {
        float x[C_IN];
        const float2* xr = (const float2*)(gf + (long long)p * C_IN);
#pragma unroll
        for (int k = 0; k < C_IN / 2; k++) {
            float2 v = __ldg(xr + k);
            x[2 * k] = v.x; x[2 * k + 1] = v.y;
        }
        int t = 0;
#pragma unroll
        for (int i = 0; i < C_IN; i++) {
            sx[i] += x[i];
#pragma unroll
            for (int j = 0; j <= i; j++) { sxx[t] = fmaf(x[i], x[j], sxx[t]); t++; }
        }
    }

    const int lane = threadIdx.x & 31;
    const int wid  = threadIdx.x >> 5;
#pragma unroll
    for (int i = 0; i < C_IN; i++) {
        float v = sx[i];
#pragma unroll
        for (int o = 16; o > 0; o >>= 1) v += __shfl_down_sync(FULLMASK, v, o);
        if (lane == 0) red[wid][i] = v;
    }
#pragma unroll
    for (int i = 0; i < 55; i++) {
        float v = sxx[i];
#pragma unroll
        for (int o = 16; o > 0; o >>= 1) v += __shfl_down_sync(FULLMASK, v, o);
        if (lane == 0) red[wid][C_IN + i] = v;
    }
    __syncthreads();
    if (threadIdx.x < 65) {
        float v = 0.f;
#pragma unroll
        for (int w = 0; w < 8; w++) v += red[w][threadIdx.x];
        if (threadIdx.x < C_IN) atomicAdd(&g_xsum[threadIdx.x], v);
        else                    atomicAdd(&g_xcov[threadIdx.x - C_IN], v);
    }
}

// ---------------------------------------------------------------------------
// K2: BN affine params from x moments; resets moment accumulators
// ---------------------------------------------------------------------------
__global__ void k_bn(const float* __restrict__ W0, const float* __restrict__ gamma,
                     const float* __restrict__ beta, float invN)
{
    int c = threadIdx.x;
    if (c < C_OUT) {
        float w[C_IN];
#pragma unroll
        for (int i = 0; i < C_IN; i++) w[i] = W0[i * C_OUT + c];
        float mu = 0.f;
#pragma unroll
        for (int i = 0; i < C_IN; i++) mu = fmaf(g_xsum[i] * invN, w[i], mu);
        float ex2 = 0.f;
        int t = 0;
#pragma unroll
        for (int i = 0; i < C_IN; i++) {
#pragma unroll
            for (int j = 0; j <= i; j++) {
                float s = g_xcov[t++] * invN;
                float coef = (i == j) ? 1.f : 2.f;
                ex2 = fmaf(coef * s, w[i] * w[j], ex2);
            }
        }
        float var = fmaf(-mu, mu, ex2);
        float rstd = rsqrtf(var + 1e-3f);
        float a = rstd * gamma[c];
        g_a[c] = a;
        g_b[c] = fmaf(-mu, a, beta[c]);
    }
    __syncthreads();
    if (c < C_IN) g_xsum[c] = 0.f;
    if (c < 55)  g_xcov[c] = 0.f;
}

// ---------------------------------------------------------------------------
// K3: bucket point ids by pillar (register-light, full occupancy)
// ---------------------------------------------------------------------------
__global__ void __launch_bounds__(256) k_count(const int* __restrict__ psi, int N)
{
    const int stride = gridDim.x * blockDim.x;
    for (int p = blockIdx.x * blockDim.x + threadIdx.x; p < N; p += stride) {
        int idx = __ldg(psi + p);
        int pos = atomicAdd(&g_cnt[idx], 1);
        if (pos < MAXPTS) g_order[idx * MAXPTS + pos] = p;
    }
}

// ---------------------------------------------------------------------------
// K4 (PROFILED SLOT): tensor-core fp16 hi/lo split GEMM: s = h@Ws + bs
// ---------------------------------------------------------------------------
#define TP 128
#define SH 72
#define SK 72
#define SMEM_TC ((TP * SH * 2 + C_OUT * SK * 2) * 2)

__global__ void __launch_bounds__(128) k_sgemm(
    const float* __restrict__ gf, const float* __restrict__ W0,
    const float* __restrict__ Ws, const float* __restrict__ bs, int N)
{
    extern __shared__ __half smh[];
    __half* sHhi = smh;
    __half* sHlo = sHhi + TP * SH;
    __half* sBhi = sHlo + TP * SH;
    __half* sBlo = sBhi + C_OUT * SK;

    const int tid = threadIdx.x, lane = tid & 31, w = tid >> 5;
    const int p0 = blockIdx.x * TP;

    for (int i = tid; i < C_OUT * C_OUT; i += 128) {
        int k = i >> 6, n = i & 63;
        float v = __ldg(Ws + i);
        __half hi = __float2half_rn(v);
        __half lo = __float2half_rn(v - __half2float(hi));
        sBhi[n * SK + k] = hi;
        sBlo[n * SK + k] = lo;
    }

    {
        const int c0 = 2 * lane;
        u64 w0v[C_IN];
#pragma unroll
        for (int k = 0; k < C_IN; k++) {
            float2 ww = *(const float2*)(W0 + k * C_OUT + c0);
            w0v[k] = pk2(ww.x, ww.y);
        }
        const float2 a2 = *(const float2*)(g_a + c0);
        const float2 b2 = *(const float2*)(g_b + c0);
        const u64 av = pk2(a2.x, a2.y);
        const u64 bv = pk2(b2.x, b2.y);

#pragma unroll 2
        for (int j = 0; j < 32; j++) {
            const int pcol = w * 32 + j;
            const int p = p0 + pcol;
            u64 hv = 0;
            if (p < N) {
                const float2* xr = (const float2*)(gf + (long long)p * C_IN);
#pragma unroll
                for (int k2 = 0; k2 < C_IN / 2; k2++) {
                    float2 x2 = __ldg(xr + k2);
                    hv = fma2(pk2(x2.x, x2.x), w0v[2 * k2],     hv);
                    hv = fma2(pk2(x2.y, x2.y), w0v[2 * k2 + 1], hv);
                }
                hv = fma2(hv, av, bv);
            }
            float hA, hB; upk2(hv, hA, hB);
            hA = fmaxf(hA, 0.f); hB = fmaxf(hB, 0.f);
            __half hiA = __float2half_rn(hA);
            __half hiB = __float2half_rn(hB);
            __half loA = __float2half_rn(hA - __half2float(hiA));
            __half loB = __float2half_rn(hB - __half2float(hiB));
            *(__half2*)&sHhi[pcol * SH + c0] = __halves2half2(hiA, hiB);
            *(__half2*)&sHlo[pcol * SH + c0] = __halves2half2(loA, loB);
        }
    }
    __syncthreads();

    const int g = lane >> 2, t = lane & 3;

    float acc[2][8][4];
#pragma unroll
    for (int ni = 0; ni < 8; ni++) {
        float b0 = __ldg(bs + ni * 8 + 2 * t);
        float b1 = __ldg(bs + ni * 8 + 2 * t + 1);
#pragma unroll
        for (int mi = 0; mi < 2; mi++) {
            acc[mi][ni][0] = b0; acc[mi][ni][1] = b1;
            acc[mi][ni][2] = b0; acc[mi][ni][3] = b1;
        }
    }

#pragma unroll
    for (int ks = 0; ks < 4; ks++) {
        const int k0 = ks * 16;
        u32 bhi[8][2], blo[8][2];
#pragma unroll
        for (int ni = 0; ni < 8; ni++) {
            int n = ni * 8 + g;
            bhi[ni][0] = *(const u32*)&sBhi[n * SK + k0 + 2 * t];
            bhi[ni][1] = *(const u32*)&sBhi[n * SK + k0 + 2 * t + 8];
            blo[ni][0] = *(const u32*)&sBlo[n * SK + k0 + 2 * t];
            blo[ni][1] = *(const u32*)&sBlo[n * SK + k0 + 2 * t + 8];
        }
#pragma unroll
        for (int mi = 0; mi < 2; mi++) {
            const int rb = w * 32 + mi * 16;
            u32 ahi[4], alo[4];
            ahi[0] = *(const u32*)&sHhi[(rb + g)     * SH + k0 + 2 * t];
            ahi[1] = *(const u32*)&sHhi[(rb + g + 8) * SH + k0 + 2 * t];
            ahi[2] = *(const u32*)&sHhi[(rb + g)     * SH + k0 + 2 * t + 8];
            ahi[3] = *(const u32*)&sHhi[(rb + g + 8) * SH + k0 + 2 * t + 8];
            alo[0] = *(const u32*)&sHlo[(rb + g)     * SH + k0 + 2 * t];
            alo[1] = *(const u32*)&sHlo[(rb + g + 8) * SH + k0 + 2 * t];
            alo[2] = *(const u32*)&sHlo[(rb + g)     * SH + k0 + 2 * t + 8];
            alo[3] = *(const u32*)&sHlo[(rb + g + 8) * SH + k0 + 2 * t + 8];
#pragma unroll
            for (int ni = 0; ni < 8; ni++) {
                mma16(acc[mi][ni], ahi, blo[ni]);
                mma16(acc[mi][ni], alo, bhi[ni]);
                mma16(acc[mi][ni], ahi, bhi[ni]);
            }
        }
    }

#pragma unroll
    for (int mi = 0; mi < 2; mi++) {
        const int rb = w * 32 + mi * 16;
        const long long r0 = (long long)p0 + rb + g;
        const long long r1 = r0 + 8;
#pragma unroll
        for (int ni = 0; ni < 8; ni++) {
            int c = ni * 8 + 2 * t;
            if (r0 < N)
                *(float2*)(g_s + r0 * C_OUT + c) = make_float2(acc[mi][ni][0], acc[mi][ni][1]);
            if (r1 < N)
                *(float2*)(g_s + r1 * C_OUT + c) = make_float2(acc[mi][ni][2], acc[mi][ni][3]);
        }
    }
}

// ---------------------------------------------------------------------------
// K5: TWO pillars per warp, interleaved depth-2 prefetch => ~2x MLP per warp.
//     All per-pillar predicates are warp-uniform (no divergence).
// ---------------------------------------------------------------------------
__global__ void __launch_bounds__(128) k_pillar(
    const float* __restrict__ gf, const float* __restrict__ W0, int M)
{
    const int lane = threadIdx.x & 31;
    const int base = (blockIdx.x * 4 + (threadIdx.x >> 5)) * 2;  // first pillar of pair
    if (base >= M) return;
    const int c0 = 2 * lane;

    u64 w0v[C_IN];
#pragma unroll
    for (int k = 0; k < C_IN; k++) {
        float2 ww = *(const float2*)(W0 + k * C_OUT + c0);
        w0v[k] = pk2(ww.x, ww.y);
    }
    const float2 a2 = *(const float2*)(g_a + c0);
    const float2 b2 = *(const float2*)(g_b + c0);
    const u64 av = pk2(a2.x, a2.y);
    const u64 bv = pk2(b2.x, b2.y);

    int cnt[2], myp0[2], myp1[2];
#pragma unroll
    for (int q = 0; q < 2; q++) {
        const int pil = base + q;
        const bool ok = pil < M;
        cnt[q] = ok ? min(g_cnt[pil], MAXPTS) : 0;
        if (ok && lane == 0) g_cnt[pil] = 0;          // replay reset
        const int* ord = g_order + (long long)pil * MAXPTS;
        myp0[q] = ok ? __ldg(ord + lane) : 0;
        myp1[q] = ok ? __ldg(ord + 32 + lane) : 0;
    }

    float denx[2] = {0.f, 0.f}, deny[2] = {0.f, 0.f};
    float numx[2] = {0.f, 0.f}, numy[2] = {0.f, 0.f};
    float mxhx[2] = {0.f, 0.f}, mxhy[2] = {0.f, 0.f};

    float2 sv[2][2];             // [q][buf]
    float2 xv[2][2][C_IN / 2];   // [q][buf][k]

#define GETP(q, j)  __shfl_sync(FULLMASK, ((j) < 32 ? myp0[q] : myp1[q]), (j) & 31)
#define PREF(q, b, j) { \
        int _p = GETP(q, j); \
        sv[q][b] = __ldg((const float2*)(g_s + (long long)_p * C_OUT) + lane); \
        const float2* _xr = (const float2*)(gf + (long long)_p * C_IN); \
        _Pragma("unroll") \
        for (int _k = 0; _k < C_IN / 2; _k++) xv[q][b][_k] = __ldg(_xr + _k); }

#define BODY(q, b) { \
        u64 hv = 0; \
        _Pragma("unroll") \
        for (int _k = 0; _k < C_IN / 2; _k++) { \
            hv = fma2(pk2(xv[q][b][_k].x, xv[q][b][_k].x), w0v[2 * _k],     hv); \
            hv = fma2(pk2(xv[q][b][_k].y, xv[q][b][_k].y), w0v[2 * _k + 1], hv); \
        } \
        hv = fma2(hv, av, bv); \
        float hx, hy; upk2(hv, hx, hy); \
        hx = fmaxf(hx, 0.f); hy = fmaxf(hy, 0.f); \
        float ex = __expf(fmaxf(sv[q][b].x, 0.f)); \
        float ey = __expf(fmaxf(sv[q][b].y, 0.f)); \
        denx[q] += ex; numx[q] = fmaf(ex, hx, numx[q]); mxhx[q] = fmaxf(mxhx[q], hx); \
        deny[q] += ey; numy[q] = fmaf(ey, hy, numy[q]); mxhy[q] = fmaxf(mxhy[q], hy); }

    if (cnt[0] > 0) PREF(0, 0, 0);
    if (cnt[1] > 0) PREF(1, 0, 0);
    if (cnt[0] > 1) PREF(0, 1, 1);
    if (cnt[1] > 1) PREF(1, 1, 1);

    const int jmax = max(cnt[0], cnt[1]);
    int j = 0;
    while (j < jmax) {
        if (j < cnt[0]) { BODY(0, 0); if (j + 2 < cnt[0]) PREF(0, 0, j + 2); }
        if (j < cnt[1]) { BODY(1, 0); if (j + 2 < cnt[1]) PREF(1, 0, j + 2); }
        j++;
        if (j >= jmax) break;
        if (j < cnt[0]) { BODY(0, 1); if (j + 2 < cnt[0]) PREF(0, 1, j + 2); }
        if (j < cnt[1]) { BODY(1, 1); if (j + 2 < cnt[1]) PREF(1, 1, j + 2); }
        j++;
    }

#pragma unroll
    for (int q = 0; q < 2; q++) {
        const int pil = base + q;
        if (pil < M) {
            float pfx = 0.5f * (numx[q] / denx[q] + mxhx[q]);
            float pfy = 0.5f * (numy[q] / deny[q] + mxhy[q]);
            if (cnt[q] == 0) { pfx = 0.f; pfy = 0.f; }
            *(float2*)&g_pf[(long long)pil * C_OUT + c0] = make_float2(pfx, pfy);
        }
    }
}

// ---------------------------------------------------------------------------
// K6: inverse map slot -> pillar+1 (0 = empty; scatter resets to 0)
// ---------------------------------------------------------------------------
__global__ void k_slot(const int* __restrict__ pind, int M) {
    int p = blockIdx.x * blockDim.x + threadIdx.x;
    if (p < M) {
        int b = __ldg(pind + p * 3 + 0);
        int x = __ldg(pind + p * 3 + 1);
        int y = __ldg(pind + p * 3 + 2);
        g_slot[b * (W_BEV * H_BEV) + x * H_BEV + y] = p + 1;
    }
}

// ---------------------------------------------------------------------------
// K7: canvas fill, single-touch; resets its slot row to 0 after staging.
// ---------------------------------------------------------------------------
__global__ void __launch_bounds__(256) k_scatter(float* __restrict__ out)
{
    __shared__ int slots[H_BEV];
    const int bx = blockIdx.x;
    const int b = bx >> 9, x = bx & 511;
    const int tid = threadIdx.x;

    ((int2*)slots)[tid] = *(const int2*)&g_slot[bx * H_BEV + 2 * tid];
    __syncthreads();
    *(int2*)&g_slot[bx * H_BEV + 2 * tid] = make_int2(0, 0);   // replay reset

    const int y0 = 2 * tid;
    const int s0 = slots[y0] - 1, s1 = slots[y0 + 1] - 1;
    const float* p0 = g_pf + (long long)s0 * C_OUT;
    const float* p1 = g_pf + (long long)s1 * C_OUT;
    const long long obase = ((long long)b * C_OUT * W_BEV + x) * H_BEV + y0;
    const float4 z = make_float4(0.f, 0.f, 0.f, 0.f);

#pragma unroll
    for (int cg = 0; cg < 8; cg++) {
        float4 a0 = z, a1 = z, c0v = z, c1v = z;
        if (s0 >= 0) {
            a0  = __ldg((const float4*)(p0 + cg * 8));
            c0v = __ldg((const float4*)(p0 + cg * 8 + 4));
        }
        if (s1 >= 0) {
            a1  = __ldg((const float4*)(p1 + cg * 8));
            c1v = __ldg((const float4*)(p1 + cg * 8 + 4));
        }
        float va[8] = {a0.x, a0.y, a0.z, a0.w, c0v.x, c0v.y, c0v.z, c0v.w};
        float vb[8] = {a1.x, a1.y, a1.z, a1.w, c1v.x, c1v.y, c1v.z, c1v.w};
#pragma unroll
        for (int jj = 0; jj < 8; jj++) {
            int c = cg * 8 + jj;
            *(float2*)&out[obase + (long long)c * (W_BEV * H_BEV)] = make_float2(va[jj], vb[jj]);
        }
    }
}

// ---------------------------------------------------------------------------
extern "C" void kernel_launch(void* const* d_in, const int* in_sizes, int n_in,
                              void* d_out, int out_size)
{
    const float* gf    = (const float*)d_in[0];
    const int*   psi   = (const int*)  d_in[1];
    const int*   pind  = (const int*)  d_in[2];
    const float* W0    = (const float*)d_in[3];
    const float* gamma = (const float*)d_in[4];
    const float* beta  = (const float*)d_in[5];
    const float* Ws    = (const float*)d_in[6];
    const float* bs    = (const float*)d_in[7];
    float* out = (float*)d_out;

    const int N = in_sizes[0] / C_IN;
    const int M = in_sizes[2] / 3;

    static int smem_set = 0;
    if (!smem_set) {
        cudaFuncSetAttribute(k_sgemm, cudaFuncAttributeMaxDynamicSharedMemorySize, SMEM_TC);
        smem_set = 1;
    }

    k_mom    <<<1480, 256>>>(gf, N);                        // 1
    k_bn     <<<1, 64>>>(W0, gamma, beta, 1.0f / (float)N); // 2
    k_count  <<<2048, 256>>>(psi, N);                       // 3
    k_sgemm  <<<(N + TP - 1) / TP, 128, SMEM_TC>>>(gf, W0, Ws, bs, N); // 4 -> profiled
    k_pillar <<<(M + 7) / 8, 128>>>(gf, W0, M);             // 5
    k_slot   <<<(M + 255) / 256, 256>>>(pind, M);           // 6
    k_scatter<<<4 * W_BEV, 256>>>(out);                     // 7
}

// round 14
// speedup vs baseline: 1.5368x; 1.5368x over previous
#include <cuda_runtime.h>
#include <cuda_fp16.h>

#define C_IN   10
#define C_OUT  64
#define MAXM   200000
#define MAXN   2000000
#define MAXPTS 64
#define W_BEV  512
#define H_BEV  512
#define NSLOT  (4 * W_BEV * H_BEV)
#define FULLMASK 0xffffffffu

// ---- device scratch (statics; zero at load; every replay self-resets) ----
__device__ __align__(16) int   g_cnt[MAXM];                   // zeroed by k_pillar after use
__device__ __align__(16) int   g_order[MAXM * MAXPTS];        // 51.2 MB
__device__ __align__(16) float g_s[(long long)MAXN * C_OUT];  // 512 MB
__device__ __align__(16) float g_pf[(long long)MAXM * C_OUT]; // 51.2 MB
__device__ __align__(16) int   g_slot[NSLOT];                 // pillar+1; reset by k_scatter
__device__ __align__(16) float g_xsum[C_IN];                  // zeroed by k_bn after use
__device__ __align__(16) float g_xcov[55];                    // zeroed by k_bn after use
__device__ __align__(16) float g_a[C_OUT];
__device__ __align__(16) float g_b[C_OUT];

// ---- packed f32x2 helpers ----
typedef unsigned long long u64;
typedef unsigned int u32;
__device__ __forceinline__ u64 pk2(float lo, float hi) {
    u64 r; asm("mov.b64 %0, {%1,%2};" : "=l"(r) : "f"(lo), "f"(hi)); return r;
}
__device__ __forceinline__ void upk2(u64 v, float& lo, float& hi) {
    asm("mov.b64 {%0,%1}, %2;" : "=f"(lo), "=f"(hi) : "l"(v));
}
__device__ __forceinline__ u64 fma2(u64 a, u64 b, u64 c) {
    u64 d; asm("fma.rn.f32x2 %0, %1, %2, %3;" : "=l"(d) : "l"(a), "l"(b), "l"(c)); return d;
}

// ---- fp16 m16n8k16 mma, f32 accumulate ----
__device__ __forceinline__ void mma16(float d[4], const u32 a[4], const u32 b[2]) {
    asm volatile("mma.sync.aligned.m16n8k16.row.col.f32.f16.f16.f32 "
        "{%0,%1,%2,%3},{%4,%5,%6,%7},{%8,%9},{%0,%1,%2,%3};"
        : "+f"(d[0]), "+f"(d[1]), "+f"(d[2]), "+f"(d[3])
        : "r"(a[0]), "r"(a[1]), "r"(a[2]), "r"(a[3]), "r"(b[0]), "r"(b[1]));
}

// fp32 pair -> fp16 hi + fp16 lo residual (packed u32 each)
__device__ __forceinline__ void hilo2(float v0, float v1, u32& hi, u32& lo) {
    __half2 H = __float22half2_rn(make_float2(v0, v1));
    float2 Hf = __half22float2(H);
    __half2 L = __float22half2_rn(make_float2(v0 - Hf.x, v1 - Hf.y));
    hi = *(u32*)&H;
    lo = *(u32*)&L;
}

// ---------------------------------------------------------------------------
// K1: x first/second moments ONLY (block-level reduction, 65 atomics/block)
// ---------------------------------------------------------------------------
__global__ void __launch_bounds__(256) k_mom(const float* __restrict__ gf, int N)
{
    __shared__ float red[8][65];
    float sx[C_IN];
    float sxx[55];
#pragma unroll
    for (int i = 0; i < C_IN; i++) sx[i] = 0.f;
#pragma unroll
    for (int i = 0; i < 55; i++) sxx[i] = 0.f;

    const int stride = gridDim.x * blockDim.x;
    for (int p = blockIdx.x * blockDim.x + threadIdx.x; p < N; p += stride) {
        float x[C_IN];
        const float2* xr = (const float2*)(gf + (long long)p * C_IN);
#pragma unroll
        for (int k = 0; k < C_IN / 2; k++) {
            float2 v = __ldg(xr + k);
            x[2 * k] = v.x; x[2 * k + 1] = v.y;
        }
        int t = 0;
#pragma unroll
        for (int i = 0; i < C_IN; i++) {
            sx[i] += x[i];
#pragma unroll
            for (int j = 0; j <= i; j++) { sxx[t] = fmaf(x[i], x[j], sxx[t]); t++; }
        }
    }

    const int lane = threadIdx.x & 31;
    const int wid  = threadIdx.x >> 5;
#pragma unroll
    for (int i = 0; i < C_IN; i++) {
        float v = sx[i];
#pragma unroll
        for (int o = 16; o > 0; o >>= 1) v += __shfl_down_sync(FULLMASK, v, o);
        if (lane == 0) red[wid][i] = v;
    }
#pragma unroll
    for (int i = 0; i < 55; i++) {
        float v = sxx[i];
#pragma unroll
        for (int o = 16; o > 0; o >>= 1) v += __shfl_down_sync(FULLMASK, v, o);
        if (lane == 0) red[wid][C_IN + i] = v;
    }
    __syncthreads();
    if (threadIdx.x < 65) {
        float v = 0.f;
#pragma unroll
        for (int w = 0; w < 8; w++) v += red[w][threadIdx.x];
        if (threadIdx.x < C_IN) atomicAdd(&g_xsum[threadIdx.x], v);
        else                    atomicAdd(&g_xcov[threadIdx.x - C_IN], v);
    }
}

// ---------------------------------------------------------------------------
// K2: BN affine params from x moments; resets moment accumulators
// ---------------------------------------------------------------------------
__global__ void k_bn(const float* __restrict__ W0, const float* __restrict__ gamma,
                     const float* __restrict__ beta, float invN)
{
    int c = threadIdx.x;
    if (c < C_OUT) {
        float w[C_IN];
#pragma unroll
        for (int i = 0; i < C_IN; i++) w[i] = W0[i * C_OUT + c];
        float mu = 0.f;
#pragma unroll
        for (int i = 0; i < C_IN; i++) mu = fmaf(g_xsum[i] * invN, w[i], mu);
        float ex2 = 0.f;
        int t = 0;
#pragma unroll
        for (int i = 0; i < C_IN; i++) {
#pragma unroll
            for (int j = 0; j <= i; j++) {
                float s = g_xcov[t++] * invN;
                float coef = (i == j) ? 1.f : 2.f;
                ex2 = fmaf(coef * s, w[i] * w[j], ex2);
            }
        }
        float var = fmaf(-mu, mu, ex2);
        float rstd = rsqrtf(var + 1e-3f);
        float a = rstd * gamma[c];
        g_a[c] = a;
        g_b[c] = fmaf(-mu, a, beta[c]);
    }
    __syncthreads();
    if (c < C_IN) g_xsum[c] = 0.f;
    if (c < 55)  g_xcov[c] = 0.f;
}

// ---------------------------------------------------------------------------
// K3: bucket point ids by pillar (register-light, full occupancy)
// ---------------------------------------------------------------------------
__global__ void __launch_bounds__(256) k_count(const int* __restrict__ psi, int N)
{
    const int stride = gridDim.x * blockDim.x;
    for (int p = blockIdx.x * blockDim.x + threadIdx.x; p < N; p += stride) {
        int idx = __ldg(psi + p);
        int pos = atomicAdd(&g_cnt[idx], 1);
        if (pos < MAXPTS) g_order[idx * MAXPTS + pos] = p;
    }
}

// ---------------------------------------------------------------------------
// K4 (PROFILED SLOT): dual tensor-core GEMM, register-fused:
//   GEMM1: h = relu(BN(x @ W0))   (x as direct A-frags; W0 smem b-frags)
//   GEMM2: s = h @ Ws + bs        (h passed GEMM1->GEMM2 in registers:
//                                  C-frag of GEMM1 IS the A-frag of GEMM2)
//   No h smem, no serial h loop. fp16 hi/lo split on both GEMMs.
// ---------------------------------------------------------------------------
#define TP  128
#define SK  72    // Ws row stride in halves (36 u32 -> conflict-free b-frags)
#define W0S 24    // W0 row stride in halves (12 u32 -> conflict-free b-frags)

__global__ void __launch_bounds__(128) k_sgemm(
    const float* __restrict__ gf, const float* __restrict__ W0,
    const float* __restrict__ Ws, const float* __restrict__ bs, int N)
{
    __shared__ __half sBhi[C_OUT * SK];    // Ws  [n][k]  hi
    __shared__ __half sBlo[C_OUT * SK];    //             lo
    __shared__ __half sW0hi[C_OUT * W0S];  // W0  [n][k]  hi  (k padded 10->16 w/ zeros)
    __shared__ __half sW0lo[C_OUT * W0S];

    const int tid = threadIdx.x, lane = tid & 31, w = tid >> 5;
    const int p0 = blockIdx.x * TP;
    const int g = lane >> 2, t = lane & 3;

    // ---- stage Ws hi/lo as [n][k] ----
    for (int i = tid; i < C_OUT * C_OUT; i += 128) {
        int k = i >> 6, n = i & 63;
        float v = __ldg(Ws + i);
        __half hi = __float2half_rn(v);
        __half lo = __float2half_rn(v - __half2float(hi));
        sBhi[n * SK + k] = hi;
        sBlo[n * SK + k] = lo;
    }
    // ---- stage W0 hi/lo as [n][k], zero-padded k=10..15 ----
    for (int i = tid; i < C_OUT * 16; i += 128) {
        int k = i & 15, n = i >> 4;
        float v = (k < C_IN) ? __ldg(W0 + k * C_OUT + n) : 0.f;
        __half hi = __float2half_rn(v);
        __half lo = __float2half_rn(v - __half2float(hi));
        sW0hi[n * W0S + k] = hi;
        sW0lo[n * W0S + k] = lo;
    }
    __syncthreads();

#pragma unroll 1
    for (int mi = 0; mi < 2; mi++) {
        const int rb = w * 32 + mi * 16;
        const long long r0 = (long long)p0 + rb + g;
        const long long r1 = r0 + 8;
        const bool v0 = r0 < N, v1 = r1 < N;

        // ---- x as A-frags (rows r0/r1, k cols 2t,2t+1 and 2t+8,2t+9) ----
        float2 xa = make_float2(0.f, 0.f), xb = xa, xc = xa, xd = xa;
        if (v0) xa = __ldg((const float2*)(gf + r0 * C_IN) + t);
        if (v1) xb = __ldg((const float2*)(gf + r1 * C_IN) + t);
        if (t == 0) {
            if (v0) xc = __ldg((const float2*)(gf + r0 * C_IN) + 4);
            if (v1) xd = __ldg((const float2*)(gf + r1 * C_IN) + 4);
        }
        u32 axhi[4], axlo[4];
        hilo2(xa.x, xa.y, axhi[0], axlo[0]);
        hilo2(xb.x, xb.y, axhi[1], axlo[1]);
        hilo2(xc.x, xc.y, axhi[2], axlo[2]);
        hilo2(xd.x, xd.y, axhi[3], axlo[3]);

        // ---- GEMM1: acc1[ni] covers cols 8ni+{2t,2t+1}, rows {r0, r1} ----
        float acc1[8][4];
#pragma unroll
        for (int ni = 0; ni < 8; ni++)
#pragma unroll
            for (int q = 0; q < 4; q++) acc1[ni][q] = 0.f;

#pragma unroll
        for (int ni = 0; ni < 8; ni++) {
            const int n = ni * 8 + g;
            u32 bh[2], bl[2];
            bh[0] = *(const u32*)&sW0hi[n * W0S + 2 * t];
            bh[1] = *(const u32*)&sW0hi[n * W0S + 2 * t + 8];
            bl[0] = *(const u32*)&sW0lo[n * W0S + 2 * t];
            bl[1] = *(const u32*)&sW0lo[n * W0S + 2 * t + 8];
            mma16(acc1[ni], axhi, bl);
            mma16(acc1[ni], axlo, bh);
            mma16(acc1[ni], axhi, bh);
        }

        // ---- epilogue: h = relu(a*acc + b); repack C-frag -> GEMM2 A-frags ----
        u32 a2hi[4][4], a2lo[4][4];
#pragma unroll
        for (int ni = 0; ni < 8; ni++) {
            float2 ga = __ldg((const float2*)(g_a + ni * 8) + t);
            float2 gb = __ldg((const float2*)(g_b + ni * 8) + t);
            float h0 = fmaxf(fmaf(acc1[ni][0], ga.x, gb.x), 0.f);
            float h1 = fmaxf(fmaf(acc1[ni][1], ga.y, gb.y), 0.f);
            float h2 = fmaxf(fmaf(acc1[ni][2], ga.x, gb.x), 0.f);
            float h3 = fmaxf(fmaf(acc1[ni][3], ga.y, gb.y), 0.f);
            const int ks = ni >> 1, o = (ni & 1) ? 2 : 0;
            hilo2(h0, h1, a2hi[ks][o + 0], a2lo[ks][o + 0]);
            hilo2(h2, h3, a2hi[ks][o + 1], a2lo[ks][o + 1]);
        }

        // ---- GEMM2: s = h @ Ws ----
        float acc2[8][4];
#pragma unroll
        for (int ni = 0; ni < 8; ni++)
#pragma unroll
            for (int q = 0; q < 4; q++) acc2[ni][q] = 0.f;

#pragma unroll
        for (int ks = 0; ks < 4; ks++) {
#pragma unroll
            for (int ni = 0; ni < 8; ni++) {
                const int n = ni * 8 + g;
                u32 bh[2], bl[2];
                bh[0] = *(const u32*)&sBhi[n * SK + 16 * ks + 2 * t];
                bh[1] = *(const u32*)&sBhi[n * SK + 16 * ks + 2 * t + 8];
                bl[0] = *(const u32*)&sBlo[n * SK + 16 * ks + 2 * t];
                bl[1] = *(const u32*)&sBlo[n * SK + 16 * ks + 2 * t + 8];
                mma16(acc2[ni], a2hi[ks], bl);
                mma16(acc2[ni], a2lo[ks], bh);
                mma16(acc2[ni], a2hi[ks], bh);
            }
        }

        // ---- store s (pre-relu), bias folded here in fp32 ----
#pragma unroll
        for (int ni = 0; ni < 8; ni++) {
            float2 bv = __ldg((const float2*)(bs + ni * 8) + t);
            const int c = ni * 8 + 2 * t;
            if (v0)
                *(float2*)(g_s + r0 * C_OUT + c) =
                    make_float2(acc2[ni][0] + bv.x, acc2[ni][1] + bv.y);
            if (v1)
                *(float2*)(g_s + r1 * C_OUT + c) =
                    make_float2(acc2[ni][2] + bv.x, acc2[ni][3] + bv.y);
        }
    }
}

// ---------------------------------------------------------------------------
// K5: warp-per-pillar gather, depth-2 prefetch (R12-proven), self-resets g_cnt
// ---------------------------------------------------------------------------
__global__ void __launch_bounds__(128) k_pillar(
    const float* __restrict__ gf, const float* __restrict__ W0, int M)
{
    const int lane = threadIdx.x & 31;
    const int pillar = blockIdx.x * 4 + (threadIdx.x >> 5);
    if (pillar >= M) return;
    const int c0 = 2 * lane;

    u64 w0v[C_IN];
#pragma unroll
    for (int k = 0; k < C_IN; k++) {
        float2 ww = *(const float2*)(W0 + k * C_OUT + c0);
        w0v[k] = pk2(ww.x, ww.y);
    }
    const float2 a2 = *(const float2*)(g_a + c0);
    const float2 b2 = *(const float2*)(g_b + c0);
    const u64 av = pk2(a2.x, a2.y);
    const u64 bv = pk2(b2.x, b2.y);

    const int cnt = min(g_cnt[pillar], MAXPTS);
    if (lane == 0) g_cnt[pillar] = 0;           // replay reset
    const int* __restrict__ ord = g_order + pillar * MAXPTS;
    const int myp0 = __ldg(ord + lane);
    const int myp1 = __ldg(ord + 32 + lane);

    float denx = 0.f, deny = 0.f;
    float numx = 0.f, numy = 0.f;
    float mxhx = 0.f, mxhy = 0.f;

    float2 sv0, sv1;
    float2 xv0[C_IN / 2], xv1[C_IN / 2];

#define GETP(j)  __shfl_sync(FULLMASK, ((j) < 32 ? myp0 : myp1), (j) & 31)
#define PREF(SV, XV, j) { \
        int _p = GETP(j); \
        SV = __ldg((const float2*)(g_s + (long long)_p * C_OUT) + lane); \
        const float2* _xr = (const float2*)(gf + (long long)_p * C_IN); \
        _Pragma("unroll") \
        for (int _k = 0; _k < C_IN / 2; _k++) XV[_k] = __ldg(_xr + _k); }

#define BODY(SV, XV) { \
        u64 hv = 0; \
        _Pragma("unroll") \
        for (int _k = 0; _k < C_IN / 2; _k++) { \
            hv = fma2(pk2(XV[_k].x, XV[_k].x), w0v[2 * _k],     hv); \
            hv = fma2(pk2(XV[_k].y, XV[_k].y), w0v[2 * _k + 1], hv); \
        } \
        hv = fma2(hv, av, bv); \
        float hx, hy; upk2(hv, hx, hy); \
        hx = fmaxf(hx, 0.f); hy = fmaxf(hy, 0.f); \
        float ex = __expf(fmaxf(SV.x, 0.f)); \
        float ey = __expf(fmaxf(SV.y, 0.f)); \
        denx += ex; numx = fmaf(ex, hx, numx); mxhx = fmaxf(mxhx, hx); \
        deny += ey; numy = fmaf(ey, hy, numy); mxhy = fmaxf(mxhy, hy); }

    if (cnt > 0) PREF(sv0, xv0, 0);
    if (cnt > 1) PREF(sv1, xv1, 1);

    int j = 0;
    while (j < cnt) {
        BODY(sv0, xv0);
        if (j + 2 < cnt) PREF(sv0, xv0, j + 2);
        j++;
        if (j >= cnt) break;
        BODY(sv1, xv1);
        if (j + 2 < cnt) PREF(sv1, xv1, j + 2);
        j++;
    }

    float pfx = 0.5f * (numx / denx + mxhx);
    float pfy = 0.5f * (numy / deny + mxhy);
    if (cnt == 0) { pfx = 0.f; pfy = 0.f; }

    *(float2*)&g_pf[(long long)pillar * C_OUT + c0] = make_float2(pfx, pfy);
}

// ---------------------------------------------------------------------------
// K6: inverse map slot -> pillar+1 (0 = empty; scatter resets to 0)
// ---------------------------------------------------------------------------
__global__ void k_slot(const int* __restrict__ pind, int M) {
    int p = blockIdx.x * blockDim.x + threadIdx.x;
    if (p < M) {
        int b = __ldg(pind + p * 3 + 0);
        int x = __ldg(pind + p * 3 + 1);
        int y = __ldg(pind + p * 3 + 2);
        g_slot[b * (W_BEV * H_BEV) + x * H_BEV + y] = p + 1;
    }
}

// ---------------------------------------------------------------------------
// K7: canvas fill, single-touch; resets its slot row to 0 after staging.
// ---------------------------------------------------------------------------
__global__ void __launch_bounds__(256) k_scatter(float* __restrict__ out)
{
    __shared__ int slots[H_BEV];
    const int bx = blockIdx.x;
    const int b = bx >> 9, x = bx & 511;
    const int tid = threadIdx.x;

    ((int2*)slots)[tid] = *(const int2*)&g_slot[bx * H_BEV + 2 * tid];
    __syncthreads();
    *(int2*)&g_slot[bx * H_BEV + 2 * tid] = make_int2(0, 0);   // replay reset

    const int y0 = 2 * tid;
    const int s0 = slots[y0] - 1, s1 = slots[y0 + 1] - 1;
    const float* p0 = g_pf + (long long)s0 * C_OUT;
    const float* p1 = g_pf + (long long)s1 * C_OUT;
    const long long obase = ((long long)b * C_OUT * W_BEV + x) * H_BEV + y0;
    const float4 z = make_float4(0.f, 0.f, 0.f, 0.f);

#pragma unroll
    for (int cg = 0; cg < 8; cg++) {
        float4 a0 = z, a1 = z, c0v = z, c1v = z;
        if (s0 >= 0) {
            a0  = __ldg((const float4*)(p0 + cg * 8));
            c0v = __ldg((const float4*)(p0 + cg * 8 + 4));
        }
        if (s1 >= 0) {
            a1  = __ldg((const float4*)(p1 + cg * 8));
            c1v = __ldg((const float4*)(p1 + cg * 8 + 4));
        }
        float va[8] = {a0.x, a0.y, a0.z, a0.w, c0v.x, c0v.y, c0v.z, c0v.w};
        float vb[8] = {a1.x, a1.y, a1.z, a1.w, c1v.x, c1v.y, c1v.z, c1v.w};
#pragma unroll
        for (int jj = 0; jj < 8; jj++) {
            int c = cg * 8 + jj;
            *(float2*)&out[obase + (long long)c * (W_BEV * H_BEV)] = make_float2(va[jj], vb[jj]);
        }
    }
}

// ---------------------------------------------------------------------------
extern "C" void kernel_launch(void* const* d_in, const int* in_sizes, int n_in,
                              void* d_out, int out_size)
{
    const float* gf    = (const float*)d_in[0];
    const int*   psi   = (const int*)  d_in[1];
    const int*   pind  = (const int*)  d_in[2];
    const float* W0    = (const float*)d_in[3];
    const float* gamma = (const float*)d_in[4];
    const float* beta  = (const float*)d_in[5];
    const float* Ws    = (const float*)d_in[6];
    const float* bs    = (const float*)d_in[7];
    float* out = (float*)d_out;

    const int N = in_sizes[0] / C_IN;
    const int M = in_sizes[2] / 3;

    k_mom    <<<1480, 256>>>(gf, N);                        // 1
    k_bn     <<<1, 64>>>(W0, gamma, beta, 1.0f / (float)N); // 2
    k_count  <<<2048, 256>>>(psi, N);                       // 3
    k_sgemm  <<<(N + TP - 1) / TP, 128>>>(gf, W0, Ws, bs, N); // 4 -> profiled
    k_pillar <<<(M + 3) / 4, 128>>>(gf, W0, M);             // 5
    k_slot   <<<(M + 255) / 256, 256>>>(pind, M);           // 6
    k_scatter<<<4 * W_BEV, 256>>>(out);                     // 7
}